// round 2
// baseline (speedup 1.0000x reference)
#include <cuda_runtime.h>
#include <math.h>
#include <stdint.h>

#define N_NODES 4096
#define TDIM    768
#define IDIM    512
#define HDIM    256
#define NHEAD   4
#define HEADD   64
#define NCLS    3
#define NEDGE   131072

// ---------------- scratch (static device allocations only) ----------------
#define NH2 (N_NODES * HDIM)
__device__ float g_fbuf[9 * NH2];          // 9 x [4096,256] fp32 buffers (36 MB)
__device__ int   g_deg[N_NODES];
__device__ int   g_cursor[N_NODES];
__device__ int   g_rowstart[N_NODES];
__device__ float g_dinv[N_NODES];
__device__ int   g_csrsrc[NEDGE];

// ---------------- generic tiled SGEMM: C[M,N] = A[M,K] @ B[K,N] -----------
// epilogue modes
#define EP_STORE          0   // C = acc
#define EP_BIAS           1   // C = acc + bias
#define EP_BIAS_RELU      2   // C = relu(acc + bias)
#define EP_ADD_BIAS_RELU  3   // C += relu(acc + bias)

template <int MODE>
__global__ void __launch_bounds__(256)
sgemm64(const float* __restrict__ A, const float* __restrict__ B,
        const float* __restrict__ bias, float* __restrict__ C,
        int M, int Nn, int K) {
    __shared__ float As[16][64];   // [k][m] transposed
    __shared__ float Bs[16][64];   // [k][n]

    const int tid = threadIdx.x;
    const int tx = tid & 15, ty = tid >> 4;
    const int m0 = blockIdx.y * 64, n0 = blockIdx.x * 64;

    const int lr = tid & 63;     // A loader: row within tile
    const int lk = tid >> 6;     // A loader: k group (0..3)
    const int bc = tid & 15;     // B loader: float4 column
    const int bk = tid >> 4;     // B loader: k row (0..15)

    float acc[4][4];
#pragma unroll
    for (int i = 0; i < 4; i++)
#pragma unroll
        for (int j = 0; j < 4; j++) acc[i][j] = 0.f;

    for (int k0 = 0; k0 < K; k0 += 16) {
        __syncthreads();
        float4 a4 = *(const float4*)(A + (size_t)(m0 + lr) * K + k0 + lk * 4);
        As[lk * 4 + 0][lr] = a4.x;
        As[lk * 4 + 1][lr] = a4.y;
        As[lk * 4 + 2][lr] = a4.z;
        As[lk * 4 + 3][lr] = a4.w;
        float4 b4 = *(const float4*)(B + (size_t)(k0 + bk) * Nn + n0 + bc * 4);
        *(float4*)&Bs[bk][bc * 4] = b4;
        __syncthreads();
#pragma unroll
        for (int kk = 0; kk < 16; kk++) {
            float4 av = *(const float4*)&As[kk][ty * 4];
            float4 bv = *(const float4*)&Bs[kk][tx * 4];
            float a0 = av.x, a1 = av.y, a2 = av.z, a3 = av.w;
            float b0 = bv.x, b1 = bv.y, b2 = bv.z, b3 = bv.w;
            acc[0][0] += a0 * b0; acc[0][1] += a0 * b1; acc[0][2] += a0 * b2; acc[0][3] += a0 * b3;
            acc[1][0] += a1 * b0; acc[1][1] += a1 * b1; acc[1][2] += a1 * b2; acc[1][3] += a1 * b3;
            acc[2][0] += a2 * b0; acc[2][1] += a2 * b1; acc[2][2] += a2 * b2; acc[2][3] += a2 * b3;
            acc[3][0] += a3 * b0; acc[3][1] += a3 * b1; acc[3][2] += a3 * b2; acc[3][3] += a3 * b3;
        }
    }

    float bb0 = 0.f, bb1 = 0.f, bb2 = 0.f, bb3 = 0.f;
    if (MODE != EP_STORE) {
        float4 bb = *(const float4*)(bias + n0 + tx * 4);
        bb0 = bb.x; bb1 = bb.y; bb2 = bb.z; bb3 = bb.w;
    }
#pragma unroll
    for (int i = 0; i < 4; i++) {
        float* cp = C + (size_t)(m0 + ty * 4 + i) * Nn + n0 + tx * 4;
        float v0 = acc[i][0], v1 = acc[i][1], v2 = acc[i][2], v3 = acc[i][3];
        if (MODE != EP_STORE) { v0 += bb0; v1 += bb1; v2 += bb2; v3 += bb3; }
        if (MODE == EP_BIAS_RELU || MODE == EP_ADD_BIAS_RELU) {
            v0 = fmaxf(v0, 0.f); v1 = fmaxf(v1, 0.f);
            v2 = fmaxf(v2, 0.f); v3 = fmaxf(v3, 0.f);
        }
        if (MODE == EP_ADD_BIAS_RELU) {
            float4 old = *(const float4*)cp;
            v0 += old.x; v1 += old.y; v2 += old.z; v3 += old.w;
        }
        *(float4*)cp = make_float4(v0, v1, v2, v3);
    }
}

// ---------------- flash attention (fp32, BM=BN=64, D=64) ------------------
// grid (64 qblocks, 4 heads), 256 threads (16x16, 4x4 micro-tile)
__global__ void __launch_bounds__(256)
flash_attn_kernel(const float* __restrict__ Qg,
                  const float* __restrict__ Kg,
                  const float* __restrict__ Vg,
                  float* __restrict__ Og) {
    extern __shared__ float sm[];
    float* Qt = sm;                   // [64][64], d-major, pre-scaled
    float* Kt = sm + 4096;            // [64][64], d-major
    float* Vs = sm + 8192;            // [64][68], c-major padded
    float* Ss = sm + 8192 + 64 * 68;  // [64][68], r-major padded

    const int tid = threadIdx.x;
    const int tx = tid & 15;
    const int ty = tid >> 4;
    const int h = blockIdx.y;
    const int q0 = blockIdx.x * 64;
    const int hoff = h * HEADD;

    {
        const int c = tid & 63, d4 = tid >> 6;
#pragma unroll
        for (int it = 0; it < 4; it++) {
            int ch = d4 * 4 + it;
            float4 v = *(const float4*)(Qg + (size_t)(q0 + c) * HDIM + hoff + ch * 4);
            Qt[(ch * 4 + 0) * 64 + c] = v.x * 0.125f;
            Qt[(ch * 4 + 1) * 64 + c] = v.y * 0.125f;
            Qt[(ch * 4 + 2) * 64 + c] = v.z * 0.125f;
            Qt[(ch * 4 + 3) * 64 + c] = v.w * 0.125f;
        }
    }

    float m[4], l[4], o[4][4];
#pragma unroll
    for (int i = 0; i < 4; i++) {
        m[i] = -1e30f; l[i] = 0.f;
#pragma unroll
        for (int j = 0; j < 4; j++) o[i][j] = 0.f;
    }

    for (int j0 = 0; j0 < N_NODES; j0 += 64) {
        __syncthreads();
        {
            const int c = tid & 63, d4 = tid >> 6;
#pragma unroll
            for (int it = 0; it < 4; it++) {
                int ch = d4 * 4 + it;
                float4 v = *(const float4*)(Kg + (size_t)(j0 + c) * HDIM + hoff + ch * 4);
                Kt[(ch * 4 + 0) * 64 + c] = v.x;
                Kt[(ch * 4 + 1) * 64 + c] = v.y;
                Kt[(ch * 4 + 2) * 64 + c] = v.z;
                Kt[(ch * 4 + 3) * 64 + c] = v.w;
            }
            const int c2 = tid >> 2, chk = tid & 3;
#pragma unroll
            for (int it = 0; it < 4; it++) {
                int ch = chk + it * 4;
                float4 v = *(const float4*)(Vg + (size_t)(j0 + c2) * HDIM + hoff + ch * 4);
                *(float4*)&Vs[c2 * 68 + ch * 4] = v;
            }
        }
        __syncthreads();

        float s[4][4];
#pragma unroll
        for (int i = 0; i < 4; i++)
#pragma unroll
            for (int j = 0; j < 4; j++) s[i][j] = 0.f;

#pragma unroll
        for (int d = 0; d < 64; d++) {
            float4 qa = *(const float4*)&Qt[d * 64 + ty * 4];
            float4 ka = *(const float4*)&Kt[d * 64 + tx * 4];
            float a0 = qa.x, a1 = qa.y, a2 = qa.z, a3 = qa.w;
            float b0 = ka.x, b1 = ka.y, b2 = ka.z, b3 = ka.w;
            s[0][0] += a0 * b0; s[0][1] += a0 * b1; s[0][2] += a0 * b2; s[0][3] += a0 * b3;
            s[1][0] += a1 * b0; s[1][1] += a1 * b1; s[1][2] += a1 * b2; s[1][3] += a1 * b3;
            s[2][0] += a2 * b0; s[2][1] += a2 * b1; s[2][2] += a2 * b2; s[2][3] += a2 * b3;
            s[3][0] += a3 * b0; s[3][1] += a3 * b1; s[3][2] += a3 * b2; s[3][3] += a3 * b3;
        }

#pragma unroll
        for (int i = 0; i < 4; i++) {
            float mx = fmaxf(fmaxf(s[i][0], s[i][1]), fmaxf(s[i][2], s[i][3]));
            mx = fmaxf(mx, __shfl_xor_sync(0xffffffffu, mx, 1));
            mx = fmaxf(mx, __shfl_xor_sync(0xffffffffu, mx, 2));
            mx = fmaxf(mx, __shfl_xor_sync(0xffffffffu, mx, 4));
            mx = fmaxf(mx, __shfl_xor_sync(0xffffffffu, mx, 8));
            float mnew = fmaxf(m[i], mx);
            float fac = __expf(m[i] - mnew);
            float rs = 0.f;
#pragma unroll
            for (int j = 0; j < 4; j++) { s[i][j] = __expf(s[i][j] - mnew); rs += s[i][j]; }
            rs += __shfl_xor_sync(0xffffffffu, rs, 1);
            rs += __shfl_xor_sync(0xffffffffu, rs, 2);
            rs += __shfl_xor_sync(0xffffffffu, rs, 4);
            rs += __shfl_xor_sync(0xffffffffu, rs, 8);
            l[i] = l[i] * fac + rs;
            m[i] = mnew;
#pragma unroll
            for (int j = 0; j < 4; j++) o[i][j] *= fac;
            *(float4*)&Ss[(ty * 4 + i) * 68 + tx * 4] =
                make_float4(s[i][0], s[i][1], s[i][2], s[i][3]);
        }
        __syncthreads();

#pragma unroll 16
        for (int c = 0; c < 64; c++) {
            float4 vv = *(const float4*)&Vs[c * 68 + tx * 4];
            float p0 = Ss[(ty * 4 + 0) * 68 + c];
            float p1 = Ss[(ty * 4 + 1) * 68 + c];
            float p2 = Ss[(ty * 4 + 2) * 68 + c];
            float p3 = Ss[(ty * 4 + 3) * 68 + c];
            o[0][0] += p0 * vv.x; o[0][1] += p0 * vv.y; o[0][2] += p0 * vv.z; o[0][3] += p0 * vv.w;
            o[1][0] += p1 * vv.x; o[1][1] += p1 * vv.y; o[1][2] += p1 * vv.z; o[1][3] += p1 * vv.w;
            o[2][0] += p2 * vv.x; o[2][1] += p2 * vv.y; o[2][2] += p2 * vv.z; o[2][3] += p2 * vv.w;
            o[3][0] += p3 * vv.x; o[3][1] += p3 * vv.y; o[3][2] += p3 * vv.z; o[3][3] += p3 * vv.w;
        }
    }

#pragma unroll
    for (int i = 0; i < 4; i++) {
        float inv = 1.0f / l[i];
        *(float4*)(Og + (size_t)(q0 + ty * 4 + i) * HDIM + hoff + tx * 4) =
            make_float4(o[i][0] * inv, o[i][1] * inv, o[i][2] * inv, o[i][3] * inv);
    }
}

// ---------------- GCN graph structure kernels -----------------------------
__global__ void zero_counts_kernel() {
    int i = blockIdx.x * blockDim.x + threadIdx.x;
    if (i < N_NODES) { g_deg[i] = 0; g_cursor[i] = 0; }
}

__global__ void count_deg_kernel(const int* __restrict__ dst) {
    int e = blockIdx.x * blockDim.x + threadIdx.x;
    if (e < NEDGE) atomicAdd(&g_deg[dst[e]], 1);
}

// single block, 1024 threads: exclusive scan of deg -> rowstart; dinv = rsqrt(deg+1)
__global__ void scan_deg_kernel() {
    __shared__ int ps[1024];
    const int t = threadIdx.x;
    const int base = t * 4;
    int d0 = g_deg[base + 0];
    int d1 = g_deg[base + 1];
    int d2 = g_deg[base + 2];
    int d3 = g_deg[base + 3];
    ps[t] = d0 + d1 + d2 + d3;
    __syncthreads();
    for (int off = 1; off < 1024; off <<= 1) {
        int add = (t >= off) ? ps[t - off] : 0;
        __syncthreads();
        ps[t] += add;
        __syncthreads();
    }
    int excl = (t == 0) ? 0 : ps[t - 1];
    g_rowstart[base + 0] = excl;
    g_rowstart[base + 1] = excl + d0;
    g_rowstart[base + 2] = excl + d0 + d1;
    g_rowstart[base + 3] = excl + d0 + d1 + d2;
    g_dinv[base + 0] = rsqrtf((float)(d0 + 1));
    g_dinv[base + 1] = rsqrtf((float)(d1 + 1));
    g_dinv[base + 2] = rsqrtf((float)(d2 + 1));
    g_dinv[base + 3] = rsqrtf((float)(d3 + 1));
}

__global__ void fill_csr_kernel(const int* __restrict__ src, const int* __restrict__ dst) {
    int e = blockIdx.x * blockDim.x + threadIdx.x;
    if (e < NEDGE) {
        int d = dst[e];
        int p = atomicAdd(&g_cursor[d], 1);
        g_csrsrc[g_rowstart[d] + p] = src[e];
    }
}

// block per dst node, 256 threads = feature dims
__global__ void __launch_bounds__(256)
gcn_gather_kernel(const float* __restrict__ hin,
                  const float* __restrict__ bias,
                  float* __restrict__ out, int do_relu) {
    __shared__ int ssrc[256];
    __shared__ float snorm[256];
    const int b = blockIdx.x;
    const int t = threadIdx.x;
    const float dv = g_dinv[b];
    const int base = g_rowstart[b];
    const int cnt = g_deg[b];
    float acc = dv * dv * hin[(size_t)b * HDIM + t];
    for (int c0 = 0; c0 < cnt; c0 += 256) {
        int nl = min(256, cnt - c0);
        __syncthreads();
        if (t < nl) {
            int s = g_csrsrc[base + c0 + t];
            ssrc[t] = s;
            snorm[t] = g_dinv[s] * dv;
        }
        __syncthreads();
        for (int j = 0; j < nl; j++)
            acc += snorm[j] * hin[(size_t)ssrc[j] * HDIM + t];
    }
    float r = acc + bias[t];
    if (do_relu) r = fmaxf(r, 0.f);
    out[(size_t)b * HDIM + t] = r;
}

// ---------------- classifier: out[N,3] = g2 @ W[256,3] + b ---------------
__global__ void classifier_kernel(const float* __restrict__ g2,
                                  const float* __restrict__ w,
                                  const float* __restrict__ b,
                                  float* __restrict__ out) {
    int idx = blockIdx.x * blockDim.x + threadIdx.x;
    if (idx >= N_NODES * NCLS) return;
    int n = idx / NCLS, c = idx % NCLS;
    float acc = b[c];
    const float* row = g2 + (size_t)n * HDIM;
#pragma unroll 8
    for (int k = 0; k < HDIM; k++) acc += row[k] * __ldg(&w[k * NCLS + c]);
    out[idx] = acc;
}

// ---------------- launch ---------------------------------------------------
extern "C" void kernel_launch(void* const* d_in, const int* in_sizes, int n_in,
                              void* d_out, int out_size) {
    const float* text    = (const float*)d_in[0];
    const float* image   = (const float*)d_in[1];
    const int*   edge    = (const int*)d_in[2];
    const float* text_w  = (const float*)d_in[3];
    const float* text_b  = (const float*)d_in[4];
    const float* image_w = (const float*)d_in[5];
    const float* image_b = (const float*)d_in[6];
    const float* wq = (const float*)d_in[7];
    const float* bq = (const float*)d_in[8];
    const float* wk = (const float*)d_in[9];
    const float* bk = (const float*)d_in[10];
    const float* wv = (const float*)d_in[11];
    const float* bv = (const float*)d_in[12];
    const float* wo = (const float*)d_in[13];
    const float* bo = (const float*)d_in[14];
    const float* gcn1_w = (const float*)d_in[15];
    const float* gcn1_b = (const float*)d_in[16];
    const float* gcn2_w = (const float*)d_in[17];
    const float* gcn2_b = (const float*)d_in[18];
    const float* cls_w  = (const float*)d_in[19];
    const float* cls_b  = (const float*)d_in[20];
    float* out = (float*)d_out;

    const int* src = edge;
    const int* dst = edge + NEDGE;

    float* FB = nullptr;
    cudaGetSymbolAddress((void**)&FB, g_fbuf);
    float* combined = FB + 0 * NH2;
    float* q        = FB + 1 * NH2;
    float* k        = FB + 2 * NH2;
    float* v        = FB + 3 * NH2;
    float* attno    = FB + 4 * NH2;
    float* attnout  = FB + 5 * NH2;
    float* hbuf     = FB + 6 * NH2;
    float* g1       = FB + 7 * NH2;
    float* g2       = FB + 8 * NH2;

    const int flash_smem = (64 * 64 + 64 * 64 + 64 * 68 + 64 * 68) * 4;  // 67584
    (void)cudaFuncSetAttribute(flash_attn_kernel,
                               cudaFuncAttributeMaxDynamicSharedMemorySize, flash_smem);

    dim3 gH(HDIM / 64, N_NODES / 64);  // (4, 64)

    // combined = relu(text@Wt+bt) + relu(img@Wi+bi)
    sgemm64<EP_BIAS_RELU><<<gH, 256>>>(text, text_w, text_b, combined, N_NODES, HDIM, TDIM);
    sgemm64<EP_ADD_BIAS_RELU><<<gH, 256>>>(image, image_w, image_b, combined, N_NODES, HDIM, IDIM);

    // Q, K, V
    sgemm64<EP_BIAS><<<gH, 256>>>(combined, wq, bq, q, N_NODES, HDIM, HDIM);
    sgemm64<EP_BIAS><<<gH, 256>>>(combined, wk, bk, k, N_NODES, HDIM, HDIM);
    sgemm64<EP_BIAS><<<gH, 256>>>(combined, wv, bv, v, N_NODES, HDIM, HDIM);

    // attention
    flash_attn_kernel<<<dim3(N_NODES / 64, NHEAD), 256, flash_smem>>>(q, k, v, attno);

    // output projection
    sgemm64<EP_BIAS><<<gH, 256>>>(attno, wo, bo, attnout, N_NODES, HDIM, HDIM);

    // CSR build
    zero_counts_kernel<<<N_NODES / 256, 256>>>();
    count_deg_kernel<<<NEDGE / 256, 256>>>(dst);
    scan_deg_kernel<<<1, 1024>>>();
    fill_csr_kernel<<<NEDGE / 256, 256>>>(src, dst);

    // GCN layer 1
    sgemm64<EP_STORE><<<gH, 256>>>(attnout, gcn1_w, nullptr, hbuf, N_NODES, HDIM, HDIM);
    gcn_gather_kernel<<<N_NODES, 256>>>(hbuf, gcn1_b, g1, 1);

    // GCN layer 2
    sgemm64<EP_STORE><<<gH, 256>>>(g1, gcn2_w, nullptr, hbuf, N_NODES, HDIM, HDIM);
    gcn_gather_kernel<<<N_NODES, 256>>>(hbuf, gcn2_b, g2, 0);

    // classifier
    classifier_kernel<<<(N_NODES * NCLS + 255) / 256, 256>>>(g2, cls_w, cls_b, out);
}

// round 3
// speedup vs baseline: 1.7871x; 1.7871x over previous
#include <cuda_runtime.h>
#include <cuda_fp16.h>
#include <math.h>
#include <stdint.h>

#define N_NODES 4096
#define TDIM    768
#define IDIM    512
#define HDIM    256
#define NHEAD   4
#define HEADD   64
#define NCLS    3
#define NEDGE   131072

// ---------------- scratch (static device allocations only) ----------------
#define NH2 (N_NODES * HDIM)
__device__ float  g_fbuf[9 * NH2];
__device__ __half g_half[3 * NH2];          // fp16 q(scaled), k, v
__device__ int    g_deg[N_NODES];
__device__ int    g_cursor[N_NODES];
__device__ int    g_rowstart[N_NODES];
__device__ float  g_dinv[N_NODES];
__device__ int    g_csrsrc[NEDGE];

// ---------------- shared fp32 GEMM tile body (64x64, reg prefetch) --------
__device__ __forceinline__ void gemm_tile(const float* __restrict__ A,
                                          const float* __restrict__ B,
                                          int K, int Nn, int m0, int n0,
                                          float (*As)[64], float (*Bs)[64],
                                          float acc[4][4]) {
    const int tid = threadIdx.x;
    const int tx = tid & 15, ty = tid >> 4;
    const int lr = tid & 63, lk = tid >> 6;
    const int bc = tid & 15, bk = tid >> 4;

    float4 a4 = *(const float4*)(A + (size_t)(m0 + lr) * K + lk * 4);
    float4 b4 = *(const float4*)(B + (size_t)bk * Nn + n0 + bc * 4);

    for (int k0 = 0; k0 < K; k0 += 16) {
        As[lk * 4 + 0][lr] = a4.x;
        As[lk * 4 + 1][lr] = a4.y;
        As[lk * 4 + 2][lr] = a4.z;
        As[lk * 4 + 3][lr] = a4.w;
        *(float4*)&Bs[bk][bc * 4] = b4;
        __syncthreads();
        if (k0 + 16 < K) {
            a4 = *(const float4*)(A + (size_t)(m0 + lr) * K + (k0 + 16) + lk * 4);
            b4 = *(const float4*)(B + (size_t)(k0 + 16 + bk) * Nn + n0 + bc * 4);
        }
#pragma unroll
        for (int kk = 0; kk < 16; kk++) {
            float4 av = *(const float4*)&As[kk][ty * 4];
            float4 bv = *(const float4*)&Bs[kk][tx * 4];
            float a0 = av.x, a1 = av.y, a2 = av.z, a3 = av.w;
            float b0 = bv.x, b1 = bv.y, b2 = bv.z, b3 = bv.w;
            acc[0][0] += a0 * b0; acc[0][1] += a0 * b1; acc[0][2] += a0 * b2; acc[0][3] += a0 * b3;
            acc[1][0] += a1 * b0; acc[1][1] += a1 * b1; acc[1][2] += a1 * b2; acc[1][3] += a1 * b3;
            acc[2][0] += a2 * b0; acc[2][1] += a2 * b1; acc[2][2] += a2 * b2; acc[2][3] += a2 * b3;
            acc[3][0] += a3 * b0; acc[3][1] += a3 * b1; acc[3][2] += a3 * b2; acc[3][3] += a3 * b3;
        }
        __syncthreads();
    }
}

// ---------------- fused projection: relu(text@Wt+bt)+relu(img@Wi+bi) ------
__global__ void __launch_bounds__(256)
proj_kernel(const float* __restrict__ text, const float* __restrict__ tw,
            const float* __restrict__ tb,
            const float* __restrict__ image, const float* __restrict__ iw,
            const float* __restrict__ ib, float* __restrict__ C) {
    __shared__ float As[16][64];
    __shared__ float Bs[16][64];
    const int m0 = blockIdx.y * 64, n0 = blockIdx.x * 64;
    const int tx = threadIdx.x & 15, ty = threadIdx.x >> 4;

    float acc[4][4];
#pragma unroll
    for (int i = 0; i < 4; i++)
#pragma unroll
        for (int j = 0; j < 4; j++) acc[i][j] = 0.f;
    gemm_tile(text, tw, TDIM, HDIM, m0, n0, As, Bs, acc);

    float res[4][4];
    float4 bb = *(const float4*)(tb + n0 + tx * 4);
#pragma unroll
    for (int i = 0; i < 4; i++) {
        res[i][0] = fmaxf(acc[i][0] + bb.x, 0.f);
        res[i][1] = fmaxf(acc[i][1] + bb.y, 0.f);
        res[i][2] = fmaxf(acc[i][2] + bb.z, 0.f);
        res[i][3] = fmaxf(acc[i][3] + bb.w, 0.f);
        acc[i][0] = acc[i][1] = acc[i][2] = acc[i][3] = 0.f;
    }
    gemm_tile(image, iw, IDIM, HDIM, m0, n0, As, Bs, acc);

    float4 bi = *(const float4*)(ib + n0 + tx * 4);
#pragma unroll
    for (int i = 0; i < 4; i++) {
        float v0 = res[i][0] + fmaxf(acc[i][0] + bi.x, 0.f);
        float v1 = res[i][1] + fmaxf(acc[i][1] + bi.y, 0.f);
        float v2 = res[i][2] + fmaxf(acc[i][2] + bi.z, 0.f);
        float v3 = res[i][3] + fmaxf(acc[i][3] + bi.w, 0.f);
        *(float4*)(C + (size_t)(m0 + ty * 4 + i) * HDIM + n0 + tx * 4) =
            make_float4(v0, v1, v2, v3);
    }
}

// ---------------- fused QKV: z selects weight/bias/output -----------------
__global__ void __launch_bounds__(256)
qkv_kernel(const float* __restrict__ A,
           const float* __restrict__ wq, const float* __restrict__ bq, float* q,
           const float* __restrict__ wk, const float* __restrict__ bk, float* k,
           const float* __restrict__ wv, const float* __restrict__ bv, float* v) {
    __shared__ float As[16][64];
    __shared__ float Bs[16][64];
    const int z = blockIdx.z;
    const float* B  = (z == 0) ? wq : (z == 1) ? wk : wv;
    const float* bb = (z == 0) ? bq : (z == 1) ? bk : bv;
    float*       C  = (z == 0) ? q  : (z == 1) ? k  : v;
    const int m0 = blockIdx.y * 64, n0 = blockIdx.x * 64;
    const int tx = threadIdx.x & 15, ty = threadIdx.x >> 4;

    float acc[4][4];
#pragma unroll
    for (int i = 0; i < 4; i++)
#pragma unroll
        for (int j = 0; j < 4; j++) acc[i][j] = 0.f;
    gemm_tile(A, B, HDIM, HDIM, m0, n0, As, Bs, acc);

    float4 b4 = *(const float4*)(bb + n0 + tx * 4);
#pragma unroll
    for (int i = 0; i < 4; i++)
        *(float4*)(C + (size_t)(m0 + ty * 4 + i) * HDIM + n0 + tx * 4) =
            make_float4(acc[i][0] + b4.x, acc[i][1] + b4.y,
                        acc[i][2] + b4.z, acc[i][3] + b4.w);
}

// ---------------- generic bias / plain gemm kernels -----------------------
__global__ void __launch_bounds__(256)
gemm_bias_kernel(const float* __restrict__ A, const float* __restrict__ B,
                 const float* __restrict__ bias, float* __restrict__ C) {
    __shared__ float As[16][64];
    __shared__ float Bs[16][64];
    const int m0 = blockIdx.y * 64, n0 = blockIdx.x * 64;
    const int tx = threadIdx.x & 15, ty = threadIdx.x >> 4;
    float acc[4][4];
#pragma unroll
    for (int i = 0; i < 4; i++)
#pragma unroll
        for (int j = 0; j < 4; j++) acc[i][j] = 0.f;
    gemm_tile(A, B, HDIM, HDIM, m0, n0, As, Bs, acc);
    float4 b4 = *(const float4*)(bias + n0 + tx * 4);
#pragma unroll
    for (int i = 0; i < 4; i++)
        *(float4*)(C + (size_t)(m0 + ty * 4 + i) * HDIM + n0 + tx * 4) =
            make_float4(acc[i][0] + b4.x, acc[i][1] + b4.y,
                        acc[i][2] + b4.z, acc[i][3] + b4.w);
}

__global__ void __launch_bounds__(256)
gemm_plain_kernel(const float* __restrict__ A, const float* __restrict__ B,
                  float* __restrict__ C) {
    __shared__ float As[16][64];
    __shared__ float Bs[16][64];
    const int m0 = blockIdx.y * 64, n0 = blockIdx.x * 64;
    const int tx = threadIdx.x & 15, ty = threadIdx.x >> 4;
    float acc[4][4];
#pragma unroll
    for (int i = 0; i < 4; i++)
#pragma unroll
        for (int j = 0; j < 4; j++) acc[i][j] = 0.f;
    gemm_tile(A, B, HDIM, HDIM, m0, n0, As, Bs, acc);
#pragma unroll
    for (int i = 0; i < 4; i++)
        *(float4*)(C + (size_t)(m0 + ty * 4 + i) * HDIM + n0 + tx * 4) =
            make_float4(acc[i][0], acc[i][1], acc[i][2], acc[i][3]);
}

// ---------------- fp32 -> fp16 convert (q scaled by 1/8) ------------------
__global__ void convert_qkv_kernel(const float* __restrict__ q,
                                   const float* __restrict__ k,
                                   const float* __restrict__ v,
                                   __half* __restrict__ qh,
                                   __half* __restrict__ kh,
                                   __half* __restrict__ vh) {
    const int n4 = NH2 / 4;                 // float4s per tensor
    int i = blockIdx.x * blockDim.x + threadIdx.x;
    if (i >= 3 * n4) return;
    int sel = i / n4, j = i - sel * n4;
    const float* src = (sel == 0) ? q : (sel == 1) ? k : v;
    __half* dst = (sel == 0) ? qh : (sel == 1) ? kh : vh;
    float sc = (sel == 0) ? 0.125f : 1.0f;
    float4 f = *(const float4*)(src + (size_t)j * 4);
    __half2 h0 = __floats2half2_rn(f.x * sc, f.y * sc);
    __half2 h1 = __floats2half2_rn(f.z * sc, f.w * sc);
    *(__half2*)(dst + (size_t)j * 4)     = h0;
    *(__half2*)(dst + (size_t)j * 4 + 2) = h1;
}

// ---------------- fp16 tensor-core flash attention ------------------------
#define FS 72   // smem row stride (halves)

__device__ __forceinline__ void mma_16816(float c[4], uint32_t a0, uint32_t a1,
                                          uint32_t a2, uint32_t a3,
                                          uint32_t b0, uint32_t b1) {
    asm volatile(
        "mma.sync.aligned.m16n8k16.row.col.f32.f16.f16.f32 "
        "{%0,%1,%2,%3}, {%4,%5,%6,%7}, {%8,%9}, {%0,%1,%2,%3};\n"
        : "+f"(c[0]), "+f"(c[1]), "+f"(c[2]), "+f"(c[3])
        : "r"(a0), "r"(a1), "r"(a2), "r"(a3), "r"(b0), "r"(b1));
}

__device__ __forceinline__ uint32_t packh2(float a, float b) {
    __half2 h = __floats2half2_rn(a, b);
    return *reinterpret_cast<uint32_t*>(&h);
}

// grid (64 q-blocks, 4 heads), 128 threads (4 warps x 16 q-rows)
__global__ void __launch_bounds__(128)
flash16_kernel(const __half* __restrict__ Qh, const __half* __restrict__ Kh,
               const __half* __restrict__ Vh, float* __restrict__ Og) {
    __shared__ __align__(16) __half Qs[64][FS];
    __shared__ __align__(16) __half Ks[64][FS];
    __shared__ __align__(16) __half Vt[64][FS];

    const int tid  = threadIdx.x;
    const int w    = tid >> 5;
    const int lane = tid & 31;
    const int r = lane >> 2, t = lane & 3;
    const int w16 = w * 16;
    const int q0 = blockIdx.x * 64;
    const int hoff = blockIdx.y * HEADD;

    // load Q tile (fp16, pre-scaled): 64 rows x 8 uint4
    for (int idx = tid; idx < 64 * 8; idx += 128) {
        int row = idx >> 3, c8 = (idx & 7) * 8;
        uint4 u = *(const uint4*)(Qh + (size_t)(q0 + row) * HDIM + hoff + c8);
        *(uint4*)&Qs[row][c8] = u;
    }
    __syncthreads();

    // hoist Q fragments (constant across j-loop)
    uint32_t qa0[4], qa1[4], qa2[4], qa3[4];
#pragma unroll
    for (int kt = 0; kt < 4; kt++) {
        qa0[kt] = *(const uint32_t*)&Qs[w16 + r    ][kt * 16 + 2 * t    ];
        qa1[kt] = *(const uint32_t*)&Qs[w16 + r + 8][kt * 16 + 2 * t    ];
        qa2[kt] = *(const uint32_t*)&Qs[w16 + r    ][kt * 16 + 2 * t + 8];
        qa3[kt] = *(const uint32_t*)&Qs[w16 + r + 8][kt * 16 + 2 * t + 8];
    }

    float m0v = -1e30f, m1v = -1e30f, l0 = 0.f, l1 = 0.f;
    float oc[8][4];
#pragma unroll
    for (int nt = 0; nt < 8; nt++)
#pragma unroll
        for (int j = 0; j < 4; j++) oc[nt][j] = 0.f;

    for (int j0 = 0; j0 < N_NODES; j0 += 64) {
        __syncthreads();   // prior iter done reading Ks/Vt
        // K tile: rows = keys, cols = dims
        for (int idx = tid; idx < 64 * 8; idx += 128) {
            int row = idx >> 3, c8 = (idx & 7) * 8;
            uint4 u = *(const uint4*)(Kh + (size_t)(j0 + row) * HDIM + hoff + c8);
            *(uint4*)&Ks[row][c8] = u;
        }
        // V tile transposed: Vt[dim][key]
        for (int idx = tid; idx < 64 * 8; idx += 128) {
            int key = idx & 63, c8 = (idx >> 6) * 8;
            uint4 u = *(const uint4*)(Vh + (size_t)(j0 + key) * HDIM + hoff + c8);
            const __half* hp = reinterpret_cast<const __half*>(&u);
#pragma unroll
            for (int ii = 0; ii < 8; ii++) Vt[c8 + ii][key] = hp[ii];
        }
        __syncthreads();

        // S = Q K^T  (m16 x n64 x k64 per warp)
        float sc[8][4];
#pragma unroll
        for (int nt = 0; nt < 8; nt++)
#pragma unroll
            for (int j = 0; j < 4; j++) sc[nt][j] = 0.f;

#pragma unroll
        for (int nt = 0; nt < 8; nt++) {
#pragma unroll
            for (int kt = 0; kt < 4; kt++) {
                uint32_t b0 = *(const uint32_t*)&Ks[nt * 8 + r][kt * 16 + 2 * t    ];
                uint32_t b1 = *(const uint32_t*)&Ks[nt * 8 + r][kt * 16 + 2 * t + 8];
                mma_16816(sc[nt], qa0[kt], qa1[kt], qa2[kt], qa3[kt], b0, b1);
            }
        }

        // online softmax (rows r and r+8)
        float mx0 = -1e30f, mx1 = -1e30f;
#pragma unroll
        for (int nt = 0; nt < 8; nt++) {
            mx0 = fmaxf(mx0, fmaxf(sc[nt][0], sc[nt][1]));
            mx1 = fmaxf(mx1, fmaxf(sc[nt][2], sc[nt][3]));
        }
        mx0 = fmaxf(mx0, __shfl_xor_sync(0xffffffffu, mx0, 1));
        mx0 = fmaxf(mx0, __shfl_xor_sync(0xffffffffu, mx0, 2));
        mx1 = fmaxf(mx1, __shfl_xor_sync(0xffffffffu, mx1, 1));
        mx1 = fmaxf(mx1, __shfl_xor_sync(0xffffffffu, mx1, 2));

        float mn0 = fmaxf(m0v, mx0), mn1 = fmaxf(m1v, mx1);
        float fac0 = __expf(m0v - mn0), fac1 = __expf(m1v - mn1);
        m0v = mn0; m1v = mn1;

        uint32_t pa[8][2];
        float rs0 = 0.f, rs1 = 0.f;
#pragma unroll
        for (int nt = 0; nt < 8; nt++) {
            float p00 = __expf(sc[nt][0] - mn0);
            float p01 = __expf(sc[nt][1] - mn0);
            float p10 = __expf(sc[nt][2] - mn1);
            float p11 = __expf(sc[nt][3] - mn1);
            rs0 += p00 + p01; rs1 += p10 + p11;
            pa[nt][0] = packh2(p00, p01);
            pa[nt][1] = packh2(p10, p11);
        }
        rs0 += __shfl_xor_sync(0xffffffffu, rs0, 1);
        rs0 += __shfl_xor_sync(0xffffffffu, rs0, 2);
        rs1 += __shfl_xor_sync(0xffffffffu, rs1, 1);
        rs1 += __shfl_xor_sync(0xffffffffu, rs1, 2);
        l0 = l0 * fac0 + rs0;
        l1 = l1 * fac1 + rs1;

#pragma unroll
        for (int nt = 0; nt < 8; nt++) {
            oc[nt][0] *= fac0; oc[nt][1] *= fac0;
            oc[nt][2] *= fac1; oc[nt][3] *= fac1;
        }

        // O += P V  (m16 x n64(dims) x k64(keys))
#pragma unroll
        for (int nt = 0; nt < 8; nt++) {
#pragma unroll
            for (int kt = 0; kt < 4; kt++) {
                uint32_t b0 = *(const uint32_t*)&Vt[nt * 8 + r][kt * 16 + 2 * t    ];
                uint32_t b1 = *(const uint32_t*)&Vt[nt * 8 + r][kt * 16 + 2 * t + 8];
                mma_16816(oc[nt], pa[2 * kt][0], pa[2 * kt][1],
                          pa[2 * kt + 1][0], pa[2 * kt + 1][1], b0, b1);
            }
        }
    }

    float inv0 = 1.0f / l0, inv1 = 1.0f / l1;
    const int row0 = q0 + w16 + r;
#pragma unroll
    for (int nt = 0; nt < 8; nt++) {
        int col = hoff + nt * 8 + 2 * t;
        *(float2*)(Og + (size_t)row0 * HDIM + col) =
            make_float2(oc[nt][0] * inv0, oc[nt][1] * inv0);
        *(float2*)(Og + (size_t)(row0 + 8) * HDIM + col) =
            make_float2(oc[nt][2] * inv1, oc[nt][3] * inv1);
    }
}

// ---------------- GCN graph structure kernels -----------------------------
__global__ void zero_counts_kernel() {
    int i = blockIdx.x * blockDim.x + threadIdx.x;
    if (i < N_NODES) { g_deg[i] = 0; g_cursor[i] = 0; }
}

__global__ void count_deg_kernel(const int* __restrict__ dst) {
    int e = blockIdx.x * blockDim.x + threadIdx.x;
    if (e < NEDGE) atomicAdd(&g_deg[dst[e]], 1);
}

__global__ void scan_deg_kernel() {
    __shared__ int ps[1024];
    const int t = threadIdx.x;
    const int base = t * 4;
    int d0 = g_deg[base + 0];
    int d1 = g_deg[base + 1];
    int d2 = g_deg[base + 2];
    int d3 = g_deg[base + 3];
    ps[t] = d0 + d1 + d2 + d3;
    __syncthreads();
    for (int off = 1; off < 1024; off <<= 1) {
        int add = (t >= off) ? ps[t - off] : 0;
        __syncthreads();
        ps[t] += add;
        __syncthreads();
    }
    int excl = (t == 0) ? 0 : ps[t - 1];
    g_rowstart[base + 0] = excl;
    g_rowstart[base + 1] = excl + d0;
    g_rowstart[base + 2] = excl + d0 + d1;
    g_rowstart[base + 3] = excl + d0 + d1 + d2;
    g_dinv[base + 0] = rsqrtf((float)(d0 + 1));
    g_dinv[base + 1] = rsqrtf((float)(d1 + 1));
    g_dinv[base + 2] = rsqrtf((float)(d2 + 1));
    g_dinv[base + 3] = rsqrtf((float)(d3 + 1));
}

__global__ void fill_csr_kernel(const int* __restrict__ src, const int* __restrict__ dst) {
    int e = blockIdx.x * blockDim.x + threadIdx.x;
    if (e < NEDGE) {
        int d = dst[e];
        int p = atomicAdd(&g_cursor[d], 1);
        g_csrsrc[g_rowstart[d] + p] = src[e];
    }
}

__global__ void __launch_bounds__(256)
gcn_gather_kernel(const float* __restrict__ hin, const float* __restrict__ bias,
                  float* __restrict__ out, int do_relu) {
    __shared__ int ssrc[256];
    __shared__ float snorm[256];
    const int b = blockIdx.x;
    const int t = threadIdx.x;
    const float dv = g_dinv[b];
    const int base = g_rowstart[b];
    const int cnt = g_deg[b];
    float acc = dv * dv * hin[(size_t)b * HDIM + t];
    for (int c0 = 0; c0 < cnt; c0 += 256) {
        int nl = min(256, cnt - c0);
        __syncthreads();
        if (t < nl) {
            int s = g_csrsrc[base + c0 + t];
            ssrc[t] = s;
            snorm[t] = g_dinv[s] * dv;
        }
        __syncthreads();
        for (int j = 0; j < nl; j++)
            acc += snorm[j] * hin[(size_t)ssrc[j] * HDIM + t];
    }
    float r = acc + bias[t];
    if (do_relu) r = fmaxf(r, 0.f);
    out[(size_t)b * HDIM + t] = r;
}

// ---------------- classifier ----------------------------------------------
__global__ void classifier_kernel(const float* __restrict__ g2,
                                  const float* __restrict__ w,
                                  const float* __restrict__ b,
                                  float* __restrict__ out) {
    int idx = blockIdx.x * blockDim.x + threadIdx.x;
    if (idx >= N_NODES * NCLS) return;
    int n = idx / NCLS, c = idx % NCLS;
    float acc = b[c];
    const float* row = g2 + (size_t)n * HDIM;
#pragma unroll 8
    for (int k = 0; k < HDIM; k++) acc += row[k] * __ldg(&w[k * NCLS + c]);
    out[idx] = acc;
}

// ---------------- launch ---------------------------------------------------
extern "C" void kernel_launch(void* const* d_in, const int* in_sizes, int n_in,
                              void* d_out, int out_size) {
    const float* text    = (const float*)d_in[0];
    const float* image   = (const float*)d_in[1];
    const int*   edge    = (const int*)d_in[2];
    const float* text_w  = (const float*)d_in[3];
    const float* text_b  = (const float*)d_in[4];
    const float* image_w = (const float*)d_in[5];
    const float* image_b = (const float*)d_in[6];
    const float* wq = (const float*)d_in[7];
    const float* bq = (const float*)d_in[8];
    const float* wk = (const float*)d_in[9];
    const float* bk = (const float*)d_in[10];
    const float* wv = (const float*)d_in[11];
    const float* bv = (const float*)d_in[12];
    const float* wo = (const float*)d_in[13];
    const float* bo = (const float*)d_in[14];
    const float* gcn1_w = (const float*)d_in[15];
    const float* gcn1_b = (const float*)d_in[16];
    const float* gcn2_w = (const float*)d_in[17];
    const float* gcn2_b = (const float*)d_in[18];
    const float* cls_w  = (const float*)d_in[19];
    const float* cls_b  = (const float*)d_in[20];
    float* out = (float*)d_out;

    const int* src = edge;
    const int* dst = edge + NEDGE;

    float* FB = nullptr;
    cudaGetSymbolAddress((void**)&FB, g_fbuf);
    __half* HB = nullptr;
    cudaGetSymbolAddress((void**)&HB, g_half);

    float* combined = FB + 0 * NH2;
    float* q        = FB + 1 * NH2;
    float* k        = FB + 2 * NH2;
    float* v        = FB + 3 * NH2;
    float* attno    = FB + 4 * NH2;
    float* attnout  = FB + 5 * NH2;
    float* hbuf     = FB + 6 * NH2;
    float* g1       = FB + 7 * NH2;
    float* g2       = FB + 8 * NH2;
    __half* qh = HB + 0 * NH2;
    __half* kh = HB + 1 * NH2;
    __half* vh = HB + 2 * NH2;

    dim3 gH(HDIM / 64, N_NODES / 64);        // (4, 64)
    dim3 gQKV(HDIM / 64, N_NODES / 64, 3);   // (4, 64, 3)

    // combined = relu(text@Wt+bt) + relu(img@Wi+bi)   [one launch]
    proj_kernel<<<gH, 256>>>(text, text_w, text_b, image, image_w, image_b, combined);

    // Q, K, V in one launch (z-indexed)
    qkv_kernel<<<gQKV, 256>>>(combined, wq, bq, q, wk, bk, k, wv, bv, v);

    // fp32 -> fp16 (q scaled by 1/sqrt(64))
    convert_qkv_kernel<<<(3 * NH2 / 4 + 255) / 256, 256>>>(q, k, v, qh, kh, vh);

    // tensor-core flash attention
    flash16_kernel<<<dim3(N_NODES / 64, NHEAD), 128>>>(qh, kh, vh, attno);

    // output projection
    gemm_bias_kernel<<<gH, 256>>>(attno, wo, bo, attnout);

    // CSR build
    zero_counts_kernel<<<N_NODES / 256, 256>>>();
    count_deg_kernel<<<NEDGE / 256, 256>>>(dst);
    scan_deg_kernel<<<1, 1024>>>();
    fill_csr_kernel<<<NEDGE / 256, 256>>>(src, dst);

    // GCN layer 1
    gemm_plain_kernel<<<gH, 256>>>(attnout, gcn1_w, hbuf);
    gcn_gather_kernel<<<N_NODES, 256>>>(hbuf, gcn1_b, g1, 1);

    // GCN layer 2
    gemm_plain_kernel<<<gH, 256>>>(g1, gcn2_w, hbuf);
    gcn_gather_kernel<<<N_NODES, 256>>>(hbuf, gcn2_b, g2, 0);

    // classifier
    classifier_kernel<<<(N_NODES * NCLS + 255) / 256, 256>>>(g2, cls_w, cls_b, out);
}